// round 12
// baseline (speedup 1.0000x reference)
#include <cuda_runtime.h>

#define N_NODES 100000
#define N_EDGES 1600000
#define IN_CH 128
#define HID 128
#define OUT_CH 64
#define MAXDEG 64

// ---------------- scratch (static device globals; no allocation) ----------------
__device__ int   g_cnt[N_NODES];
__device__ int   g_ell[N_NODES * MAXDEG];     // ELL adjacency (by dst)
__device__ float g_dinv[N_NODES];
__device__ float g_xs1[N_NODES * HID];        // x @ W1 (unscaled)
__device__ float g_h  [N_NODES * HID];        // layer-1 activations
__device__ float g_xs2[N_NODES * OUT_CH];     // (h @ W2) * dinv[row]

// ---------------- f32x2 packed-FMA helpers ----------------
__device__ __forceinline__ unsigned long long ffma2(unsigned long long a,
                                                    unsigned long long b,
                                                    unsigned long long c) {
    unsigned long long d;
    asm("fma.rn.f32x2 %0, %1, %2, %3;" : "=l"(d) : "l"(a), "l"(b), "l"(c));
    return d;
}
__device__ __forceinline__ unsigned long long pack2(float x) {
    unsigned long long d;
    asm("mov.b64 %0, {%1, %1};" : "=l"(d) : "f"(x));
    return d;
}
__device__ __forceinline__ float2 unpack2(unsigned long long v) {
    float2 r;
    asm("mov.b64 {%0, %1}, %2;" : "=f"(r.x), "=f"(r.y) : "l"(v));
    return r;
}

// ---------------- prep: ELL build ----------------
__global__ void k_zero_cnt() {
    int i = blockIdx.x * blockDim.x + threadIdx.x;
    if (i < N_NODES) g_cnt[i] = 0;
}

__global__ void k_scatter_ell(const int* __restrict__ ei) {
    int e = blockIdx.x * blockDim.x + threadIdx.x;
    if (e < N_EDGES) {
        int src = ei[e];
        int dst = ei[N_EDGES + e];
        int slot = atomicAdd(&g_cnt[dst], 1);
        g_ell[dst * MAXDEG + slot] = src;
    }
}

__global__ void k_dinv() {
    int i = blockIdx.x * blockDim.x + threadIdx.x;
    if (i < N_NODES) g_dinv[i] = rsqrtf((float)(g_cnt[i] + 1));  // +1 self loop
}

// ---------------- GEMM: out = (in @ W) * (scale ? dinv : 1) ----------------
// BM=128, 512 threads, TM=4 -> ~60 regs/thread -> 2 blocks/SM (32 warps).
template <int NOUT, bool SCALE>
__device__ __forceinline__ void gemm_body(const float* __restrict__ in,
                                          const float* __restrict__ W,
                                          float* __restrict__ out) {
    constexpr int BM = 128, BK = 32, TM = 4, TN = NOUT / 16, TP = TN / 2;
    __shared__ __align__(16) float xt[BK][BM + 4];   // transposed x tile
    __shared__ __align__(16) float ws[BK][NOUT];

    int tid = threadIdx.x;          // 0..511
    int tcol = tid & 15;            // 16 col groups
    int trow = tid >> 4;            // 32 row groups x TM=4 = 128 rows
    int brow = blockIdx.x * BM;

    unsigned long long acc[TM][TP];
#pragma unroll
    for (int i = 0; i < TM; i++)
#pragma unroll
        for (int j = 0; j < TP; j++) acc[i][j] = 0ull;

    for (int k0 = 0; k0 < 128; k0 += BK) {
        // x tile: 128 rows x 32 k, stored transposed (1 float4 per thread per it)
#pragma unroll
        for (int it = 0; it < BM * BK / (4 * 512); it++) {
            int idx = tid + it * 512;
            int r = idx >> 3;      // row 0..127
            int kq = idx & 7;      // k-quad 0..7
            int row = brow + r;
            float4 v = make_float4(0.f, 0.f, 0.f, 0.f);
            if (row < N_NODES)
                v = *(const float4*)(in + row * 128 + k0 + kq * 4);
            xt[kq * 4 + 0][r] = v.x;
            xt[kq * 4 + 1][r] = v.y;
            xt[kq * 4 + 2][r] = v.z;
            xt[kq * 4 + 3][r] = v.w;
        }
        // W tile: 32 x NOUT
#pragma unroll
        for (int it = 0; it < BK * NOUT / (4 * 512); it++) {
            int idx = tid + it * 512;
            int r = idx / (NOUT / 4);
            int cq = idx % (NOUT / 4);
            *(float4*)(&ws[r][cq * 4]) = *(const float4*)(W + (k0 + r) * NOUT + cq * 4);
        }
        __syncthreads();

#pragma unroll 4
        for (int kk = 0; kk < BK; kk++) {
            float4 a0 = *(const float4*)(&xt[kk][trow * TM]);
            unsigned long long pa[TM];
            pa[0] = pack2(a0.x); pa[1] = pack2(a0.y);
            pa[2] = pack2(a0.z); pa[3] = pack2(a0.w);

            unsigned long long b[TP];
#pragma unroll
            for (int j = 0; j < TP; j += 2) {
                ulonglong2 bv = *(const ulonglong2*)(&ws[kk][tcol * TN + j * 2]);
                b[j] = bv.x;
                b[j + 1] = bv.y;
            }
#pragma unroll
            for (int i = 0; i < TM; i++)
#pragma unroll
                for (int j = 0; j < TP; j++) acc[i][j] = ffma2(pa[i], b[j], acc[i][j]);
        }
        __syncthreads();
    }

#pragma unroll
    for (int i = 0; i < TM; i++) {
        int row = brow + trow * TM + i;
        if (row < N_NODES) {
            float di = SCALE ? g_dinv[row] : 1.0f;
            float r[TN];
#pragma unroll
            for (int j = 0; j < TP; j++) {
                float2 u = unpack2(acc[i][j]);
                r[j * 2] = u.x * di;
                r[j * 2 + 1] = u.y * di;
            }
#pragma unroll
            for (int j = 0; j < TN; j += 4)
                *(float4*)(out + row * NOUT + tcol * TN + j) =
                    make_float4(r[j], r[j + 1], r[j + 2], r[j + 3]);
        }
    }
}

__global__ void __launch_bounds__(512, 2) k_gemm1(const float* __restrict__ x,
                                                  const float* __restrict__ W1) {
    gemm_body<HID, false>(x, W1, g_xs1);
}
__global__ void __launch_bounds__(512, 2) k_gemm2(const float* __restrict__ W2) {
    gemm_body<OUT_CH, true>(g_h, W2, g_xs2);
}

// ---------------- aggregation layer 1: warp per node, 128 feats ----------------
// h[v] = l2norm(relu(dinv[v]*(sum dinv[src]*xs1[src] + dinv[v]*xs1[v]) + b1))
__global__ void __launch_bounds__(256) k_agg1(const float* __restrict__ b1) {
    int gw = (blockIdx.x * blockDim.x + threadIdx.x) >> 5;
    int lane = threadIdx.x & 31;
    if (gw >= N_NODES) return;
    int v = gw;

    const float4* xrow = (const float4*)g_xs1;
    float dvv = g_dinv[v];
    float4 self = xrow[v * 32 + lane];
    float4 acc;
    acc.x = self.x * dvv; acc.y = self.y * dvv;
    acc.z = self.z * dvv; acc.w = self.w * dvv;

    int deg = g_cnt[v];
    int base = v * MAXDEG;
    for (int e = 0; e < deg; e += 32) {
        int m = deg - e;
        int c = 0;
        float dv = 0.f;
        if (lane < m) {
            c = g_ell[base + e + lane];
            dv = g_dinv[c];
        }
        if (m >= 32) {
#pragma unroll
            for (int j = 0; j < 32; j++) {
                int col = __shfl_sync(0xffffffffu, c, j);
                float d = __shfl_sync(0xffffffffu, dv, j);
                float4 val = xrow[col * 32 + lane];
                acc.x = fmaf(val.x, d, acc.x);
                acc.y = fmaf(val.y, d, acc.y);
                acc.z = fmaf(val.z, d, acc.z);
                acc.w = fmaf(val.w, d, acc.w);
            }
        } else {
            for (int j = 0; j < m; j++) {
                int col = __shfl_sync(0xffffffffu, c, j);
                float d = __shfl_sync(0xffffffffu, dv, j);
                float4 val = xrow[col * 32 + lane];
                acc.x = fmaf(val.x, d, acc.x);
                acc.y = fmaf(val.y, d, acc.y);
                acc.z = fmaf(val.z, d, acc.z);
                acc.w = fmaf(val.w, d, acc.w);
            }
        }
    }

    float4 bb = ((const float4*)b1)[lane];
    float4 h;
    h.x = fmaxf(fmaf(dvv, acc.x, bb.x), 0.f);
    h.y = fmaxf(fmaf(dvv, acc.y, bb.y), 0.f);
    h.z = fmaxf(fmaf(dvv, acc.z, bb.z), 0.f);
    h.w = fmaxf(fmaf(dvv, acc.w, bb.w), 0.f);

    float ss = h.x * h.x + h.y * h.y + h.z * h.z + h.w * h.w;
#pragma unroll
    for (int off = 16; off; off >>= 1) ss += __shfl_xor_sync(0xffffffffu, ss, off);
    float sc = 1.0f / fmaxf(sqrtf(ss), 1e-12f);
    h.x *= sc; h.y *= sc; h.z *= sc; h.w *= sc;

    ((float4*)g_h)[v * 32 + lane] = h;
}

// ---------------- aggregation layer 2: warp per node, 64 feats ----------------
// out[v] = dinv[v]*(sum xs2[src] + xs2[v]) + b2   (dinv[src] folded in gemm2)
__global__ void __launch_bounds__(256) k_agg2(const float* __restrict__ b2,
                                              float* __restrict__ out) {
    int gw = (blockIdx.x * blockDim.x + threadIdx.x) >> 5;
    int lane = threadIdx.x & 31;
    if (gw >= N_NODES) return;
    int v = gw;

    const float2* xrow = (const float2*)g_xs2;
    float2 acc = xrow[v * 32 + lane];  // self term

    int deg = g_cnt[v];
    int base = v * MAXDEG;
    for (int e = 0; e < deg; e += 32) {
        int m = deg - e;
        int c = (lane < m) ? g_ell[base + e + lane] : 0;
        if (m >= 32) {
#pragma unroll
            for (int j = 0; j < 32; j++) {
                int col = __shfl_sync(0xffffffffu, c, j);
                float2 val = xrow[col * 32 + lane];
                acc.x += val.x; acc.y += val.y;
            }
        } else {
            for (int j = 0; j < m; j++) {
                int col = __shfl_sync(0xffffffffu, c, j);
                float2 val = xrow[col * 32 + lane];
                acc.x += val.x; acc.y += val.y;
            }
        }
    }

    float di = g_dinv[v];
    float2 bb = ((const float2*)b2)[lane];
    float2 o;
    o.x = fmaf(di, acc.x, bb.x);
    o.y = fmaf(di, acc.y, bb.y);
    ((float2*)out)[v * 32 + lane] = o;
}

// ---------------- launch (prep chain forked onto a side stream) ----------------
static cudaStream_t s_side = nullptr;
static cudaEvent_t e_fork = nullptr, e_join = nullptr;

extern "C" void kernel_launch(void* const* d_in, const int* in_sizes, int n_in,
                              void* d_out, int out_size) {
    const float* x  = (const float*)d_in[0];
    const int*   ei = (const int*)d_in[1];   // JAX default: int64 request -> int32
    const float* W1 = (const float*)d_in[2];
    const float* b1 = (const float*)d_in[3];
    const float* W2 = (const float*)d_in[4];
    const float* b2 = (const float*)d_in[5];
    float* out = (float*)d_out;

    if (!s_side) {  // first call is the uncaptured correctness run
        cudaStreamCreateWithFlags(&s_side, cudaStreamNonBlocking);
        cudaEventCreateWithFlags(&e_fork, cudaEventDisableTiming);
        cudaEventCreateWithFlags(&e_join, cudaEventDisableTiming);
    }

    // fork: ELL prep on side stream, gemm1 on main stream
    cudaEventRecord(e_fork, 0);
    cudaStreamWaitEvent(s_side, e_fork, 0);

    k_zero_cnt<<<(N_NODES + 255) / 256, 256, 0, s_side>>>();
    k_scatter_ell<<<(N_EDGES + 255) / 256, 256, 0, s_side>>>(ei);
    k_dinv<<<(N_NODES + 255) / 256, 256, 0, s_side>>>();
    cudaEventRecord(e_join, s_side);

    k_gemm1<<<(N_NODES + 127) / 128, 512>>>(x, W1);

    // join: everything below needs both gemm1 and the ELL/dinv
    cudaStreamWaitEvent(0, e_join, 0);

    k_agg1<<<(N_NODES * 32 + 255) / 256, 256>>>(b1);
    k_gemm2<<<(N_NODES + 127) / 128, 512>>>(W2);
    k_agg2<<<(N_NODES * 32 + 255) / 256, 256>>>(b2, out);
}

// round 13
// speedup vs baseline: 1.0691x; 1.0691x over previous
#include <cuda_runtime.h>

#define N_NODES 100000
#define N_EDGES 1600000
#define IN_CH 128
#define HID 128
#define OUT_CH 64
#define MAXDEG 64

// ---------------- scratch (static device globals; no allocation) ----------------
__device__ int   g_cnt[N_NODES];
__device__ int   g_ell[N_NODES * MAXDEG];     // ELL adjacency (by dst)
__device__ float g_dinv[N_NODES];
__device__ float g_xs1[N_NODES * HID];        // x @ W1 (unscaled)
__device__ float g_h  [N_NODES * HID];        // layer-1 activations
__device__ float g_xs2[N_NODES * OUT_CH];     // (h @ W2) * dinv[row]

// ---------------- f32x2 packed-FMA helpers ----------------
__device__ __forceinline__ unsigned long long ffma2(unsigned long long a,
                                                    unsigned long long b,
                                                    unsigned long long c) {
    unsigned long long d;
    asm("fma.rn.f32x2 %0, %1, %2, %3;" : "=l"(d) : "l"(a), "l"(b), "l"(c));
    return d;
}
__device__ __forceinline__ unsigned long long pack2(float x) {
    unsigned long long d;
    asm("mov.b64 %0, {%1, %1};" : "=l"(d) : "f"(x));
    return d;
}
__device__ __forceinline__ float2 unpack2(unsigned long long v) {
    float2 r;
    asm("mov.b64 {%0, %1}, %2;" : "=f"(r.x), "=f"(r.y) : "l"(v));
    return r;
}

// ---------------- prep: ELL build ----------------
__global__ void k_zero_cnt() {
    int i = blockIdx.x * blockDim.x + threadIdx.x;
    if (i < N_NODES) g_cnt[i] = 0;
}

__global__ void k_scatter_ell(const int* __restrict__ ei) {
    int e = blockIdx.x * blockDim.x + threadIdx.x;
    if (e < N_EDGES) {
        int src = ei[e];
        int dst = ei[N_EDGES + e];
        int slot = atomicAdd(&g_cnt[dst], 1);
        g_ell[dst * MAXDEG + slot] = src;
    }
}

__global__ void k_dinv() {
    int i = blockIdx.x * blockDim.x + threadIdx.x;
    if (i < N_NODES) g_dinv[i] = rsqrtf((float)(g_cnt[i] + 1));  // +1 self loop
}

// ---------------- GEMM: out = (in @ W) * (scale ? dinv : 1) ----------------
// BM=128, 256 threads, TM=8. x tile stored transposed AND pre-packed as
// duplicated f32x2 (u64) -> inner loop has zero pack MOVs: 32 FFMA2 + 6 LDS.
template <int NOUT, bool SCALE>
__device__ __forceinline__ void gemm_body(const float* __restrict__ in,
                                          const float* __restrict__ W,
                                          float* __restrict__ out) {
    constexpr int BM = 128, BK = 32, TM = 8, TN = NOUT / 16, TP = TN / 2;
    __shared__ __align__(16) unsigned long long xt2[BK][BM + 2];  // packed pairs
    __shared__ __align__(16) float ws[BK][NOUT];

    int tid = threadIdx.x;
    int tcol = tid & 15;
    int trow = tid >> 4;
    int brow = blockIdx.x * BM;

    unsigned long long acc[TM][TP];
#pragma unroll
    for (int i = 0; i < TM; i++)
#pragma unroll
        for (int j = 0; j < TP; j++) acc[i][j] = 0ull;

    for (int k0 = 0; k0 < 128; k0 += BK) {
        // x tile: 128 rows x 32 k, transposed + packed (4 values per thread x 4 it)
#pragma unroll
        for (int it = 0; it < BM * BK / (4 * 256); it++) {
            int idx = tid + it * 256;
            int r = idx >> 3;      // row 0..127
            int kq = idx & 7;      // k-quad 0..7
            int row = brow + r;
            float4 v = make_float4(0.f, 0.f, 0.f, 0.f);
            if (row < N_NODES)
                v = *(const float4*)(in + row * 128 + k0 + kq * 4);
            xt2[kq * 4 + 0][r] = pack2(v.x);
            xt2[kq * 4 + 1][r] = pack2(v.y);
            xt2[kq * 4 + 2][r] = pack2(v.z);
            xt2[kq * 4 + 3][r] = pack2(v.w);
        }
        // W tile: 32 x NOUT
#pragma unroll
        for (int it = 0; it < BK * NOUT / (4 * 256); it++) {
            int idx = tid + it * 256;
            int r = idx / (NOUT / 4);
            int cq = idx % (NOUT / 4);
            *(float4*)(&ws[r][cq * 4]) = *(const float4*)(W + (k0 + r) * NOUT + cq * 4);
        }
        __syncthreads();

#pragma unroll 4
        for (int kk = 0; kk < BK; kk++) {
            unsigned long long pa[TM];
#pragma unroll
            for (int i = 0; i < TM; i += 2) {
                ulonglong2 av = *(const ulonglong2*)(&xt2[kk][trow * TM + i]);
                pa[i] = av.x;
                pa[i + 1] = av.y;
            }
            unsigned long long b[TP];
#pragma unroll
            for (int j = 0; j < TP; j += 2) {
                ulonglong2 bv = *(const ulonglong2*)(&ws[kk][tcol * TN + j * 2]);
                b[j] = bv.x;
                b[j + 1] = bv.y;
            }
#pragma unroll
            for (int i = 0; i < TM; i++)
#pragma unroll
                for (int j = 0; j < TP; j++) acc[i][j] = ffma2(pa[i], b[j], acc[i][j]);
        }
        __syncthreads();
    }

#pragma unroll
    for (int i = 0; i < TM; i++) {
        int row = brow + trow * TM + i;
        if (row < N_NODES) {
            float di = SCALE ? g_dinv[row] : 1.0f;
            float r[TN];
#pragma unroll
            for (int j = 0; j < TP; j++) {
                float2 u = unpack2(acc[i][j]);
                r[j * 2] = u.x * di;
                r[j * 2 + 1] = u.y * di;
            }
#pragma unroll
            for (int j = 0; j < TN; j += 4)
                *(float4*)(out + row * NOUT + tcol * TN + j) =
                    make_float4(r[j], r[j + 1], r[j + 2], r[j + 3]);
        }
    }
}

__global__ void __launch_bounds__(256) k_gemm1(const float* __restrict__ x,
                                               const float* __restrict__ W1) {
    gemm_body<HID, false>(x, W1, g_xs1);
}
__global__ void __launch_bounds__(256) k_gemm2(const float* __restrict__ W2) {
    gemm_body<OUT_CH, true>(g_h, W2, g_xs2);
}

// ---------------- aggregation layer 1: warp per node, 128 feats ----------------
// h[v] = l2norm(relu(dinv[v]*(sum dinv[src]*xs1[src] + dinv[v]*xs1[v]) + b1))
__global__ void __launch_bounds__(256) k_agg1(const float* __restrict__ b1) {
    int gw = (blockIdx.x * blockDim.x + threadIdx.x) >> 5;
    int lane = threadIdx.x & 31;
    if (gw >= N_NODES) return;
    int v = gw;

    const float4* xrow = (const float4*)g_xs1;
    float dvv = g_dinv[v];
    float4 self = xrow[v * 32 + lane];
    float4 acc;
    acc.x = self.x * dvv; acc.y = self.y * dvv;
    acc.z = self.z * dvv; acc.w = self.w * dvv;

    int deg = g_cnt[v];
    int base = v * MAXDEG;
    for (int e = 0; e < deg; e += 32) {
        int m = deg - e;
        int c = 0;
        float dv = 0.f;
        if (lane < m) {
            c = g_ell[base + e + lane];
            dv = g_dinv[c];
        }
        if (m >= 32) {
#pragma unroll
            for (int j = 0; j < 32; j++) {
                int col = __shfl_sync(0xffffffffu, c, j);
                float d = __shfl_sync(0xffffffffu, dv, j);
                float4 val = xrow[col * 32 + lane];
                acc.x = fmaf(val.x, d, acc.x);
                acc.y = fmaf(val.y, d, acc.y);
                acc.z = fmaf(val.z, d, acc.z);
                acc.w = fmaf(val.w, d, acc.w);
            }
        } else {
            for (int j = 0; j < m; j++) {
                int col = __shfl_sync(0xffffffffu, c, j);
                float d = __shfl_sync(0xffffffffu, dv, j);
                float4 val = xrow[col * 32 + lane];
                acc.x = fmaf(val.x, d, acc.x);
                acc.y = fmaf(val.y, d, acc.y);
                acc.z = fmaf(val.z, d, acc.z);
                acc.w = fmaf(val.w, d, acc.w);
            }
        }
    }

    float4 bb = ((const float4*)b1)[lane];
    float4 h;
    h.x = fmaxf(fmaf(dvv, acc.x, bb.x), 0.f);
    h.y = fmaxf(fmaf(dvv, acc.y, bb.y), 0.f);
    h.z = fmaxf(fmaf(dvv, acc.z, bb.z), 0.f);
    h.w = fmaxf(fmaf(dvv, acc.w, bb.w), 0.f);

    float ss = h.x * h.x + h.y * h.y + h.z * h.z + h.w * h.w;
#pragma unroll
    for (int off = 16; off; off >>= 1) ss += __shfl_xor_sync(0xffffffffu, ss, off);
    float sc = 1.0f / fmaxf(sqrtf(ss), 1e-12f);
    h.x *= sc; h.y *= sc; h.z *= sc; h.w *= sc;

    ((float4*)g_h)[v * 32 + lane] = h;
}

// ---------------- aggregation layer 2: warp per node, 64 feats ----------------
// out[v] = dinv[v]*(sum xs2[src] + xs2[v]) + b2   (dinv[src] folded in gemm2)
__global__ void __launch_bounds__(256) k_agg2(const float* __restrict__ b2,
                                              float* __restrict__ out) {
    int gw = (blockIdx.x * blockDim.x + threadIdx.x) >> 5;
    int lane = threadIdx.x & 31;
    if (gw >= N_NODES) return;
    int v = gw;

    const float2* xrow = (const float2*)g_xs2;
    float2 acc = xrow[v * 32 + lane];  // self term

    int deg = g_cnt[v];
    int base = v * MAXDEG;
    for (int e = 0; e < deg; e += 32) {
        int m = deg - e;
        int c = (lane < m) ? g_ell[base + e + lane] : 0;
        if (m >= 32) {
#pragma unroll
            for (int j = 0; j < 32; j++) {
                int col = __shfl_sync(0xffffffffu, c, j);
                float2 val = xrow[col * 32 + lane];
                acc.x += val.x; acc.y += val.y;
            }
        } else {
            for (int j = 0; j < m; j++) {
                int col = __shfl_sync(0xffffffffu, c, j);
                float2 val = xrow[col * 32 + lane];
                acc.x += val.x; acc.y += val.y;
            }
        }
    }

    float di = g_dinv[v];
    float2 bb = ((const float2*)b2)[lane];
    float2 o;
    o.x = fmaf(di, acc.x, bb.x);
    o.y = fmaf(di, acc.y, bb.y);
    ((float2*)out)[v * 32 + lane] = o;
}

// ---------------- launch (prep chain forked onto a side stream) ----------------
static cudaStream_t s_side = nullptr;
static cudaEvent_t e_fork = nullptr, e_join = nullptr;

extern "C" void kernel_launch(void* const* d_in, const int* in_sizes, int n_in,
                              void* d_out, int out_size) {
    const float* x  = (const float*)d_in[0];
    const int*   ei = (const int*)d_in[1];   // JAX default: int64 request -> int32
    const float* W1 = (const float*)d_in[2];
    const float* b1 = (const float*)d_in[3];
    const float* W2 = (const float*)d_in[4];
    const float* b2 = (const float*)d_in[5];
    float* out = (float*)d_out;

    if (!s_side) {  // first call is the uncaptured correctness run
        cudaStreamCreateWithFlags(&s_side, cudaStreamNonBlocking);
        cudaEventCreateWithFlags(&e_fork, cudaEventDisableTiming);
        cudaEventCreateWithFlags(&e_join, cudaEventDisableTiming);
    }

    // fork: ELL prep on side stream, gemm1 on main stream
    cudaEventRecord(e_fork, 0);
    cudaStreamWaitEvent(s_side, e_fork, 0);

    k_zero_cnt<<<(N_NODES + 255) / 256, 256, 0, s_side>>>();
    k_scatter_ell<<<(N_EDGES + 255) / 256, 256, 0, s_side>>>(ei);
    k_dinv<<<(N_NODES + 255) / 256, 256, 0, s_side>>>();
    cudaEventRecord(e_join, s_side);

    k_gemm1<<<(N_NODES + 127) / 128, 256>>>(x, W1);

    // join: everything below needs both gemm1 and the ELL/dinv
    cudaStreamWaitEvent(0, e_join, 0);

    k_agg1<<<(N_NODES * 32 + 255) / 256, 256>>>(b1);
    k_gemm2<<<(N_NODES + 127) / 128, 256>>>(W2);
    k_agg2<<<(N_NODES * 32 + 255) / 256, 256>>>(b2, out);
}

// round 15
// speedup vs baseline: 1.3843x; 1.2949x over previous
#include <cuda_runtime.h>
#include <cuda_bf16.h>
#include <cstdint>

#define N_NODES 100000
#define N_EDGES 1600000
#define IN_CH 128
#define HID 128
#define OUT_CH 64
#define MAXDEG 64

// ---------------- scratch (static device globals; no allocation) ----------------
__device__ int   g_cnt[N_NODES];
__device__ int   g_ell[N_NODES * MAXDEG];     // ELL adjacency (by dst)
__device__ float g_dinv[N_NODES];
__device__ float g_xs1[N_NODES * HID];        // x @ W1 (unscaled)
__device__ float g_h  [N_NODES * HID];        // layer-1 activations
__device__ float g_xs2[N_NODES * OUT_CH];     // (h @ W2) * dinv[row]

// ---------------- f32x2 packed-FMA helpers (scalar gemm2) ----------------
__device__ __forceinline__ unsigned long long ffma2(unsigned long long a,
                                                    unsigned long long b,
                                                    unsigned long long c) {
    unsigned long long d;
    asm("fma.rn.f32x2 %0, %1, %2, %3;" : "=l"(d) : "l"(a), "l"(b), "l"(c));
    return d;
}
__device__ __forceinline__ unsigned long long pack2(float x) {
    unsigned long long d;
    asm("mov.b64 %0, {%1, %1};" : "=l"(d) : "f"(x));
    return d;
}
__device__ __forceinline__ float2 unpack2(unsigned long long v) {
    float2 r;
    asm("mov.b64 {%0, %1}, %2;" : "=f"(r.x), "=f"(r.y) : "l"(v));
    return r;
}

__device__ __forceinline__ uint32_t smem_u32(const void* p) {
    uint32_t a;
    asm("{ .reg .u64 t; cvta.to.shared.u64 t, %1; cvt.u32.u64 %0, t; }"
        : "=r"(a) : "l"(p));
    return a;
}

// ---------------- prep: ELL build ----------------
__global__ void k_zero_cnt() {
    int i = blockIdx.x * blockDim.x + threadIdx.x;
    if (i < N_NODES) g_cnt[i] = 0;
}
__global__ void k_scatter_ell(const int* __restrict__ ei) {
    int e = blockIdx.x * blockDim.x + threadIdx.x;
    if (e < N_EDGES) {
        int src = ei[e];
        int dst = ei[N_EDGES + e];
        int slot = atomicAdd(&g_cnt[dst], 1);
        g_ell[dst * MAXDEG + slot] = src;
    }
}
__global__ void k_dinv() {
    int i = blockIdx.x * blockDim.x + threadIdx.x;
    if (i < N_NODES) g_dinv[i] = rsqrtf((float)(g_cnt[i] + 1));  // +1 self loop
}

// ---------------- tensor GEMM1 via mma.sync (bf16 hi/lo, 3 passes) ------------
// Per CTA: 128 rows x N=128, K processed in 4 chunks of 32.
// 8 warps: warp_m = wid>>1 (32 rows), warp_n = wid&1 (64 cols).
__device__ __forceinline__ void ldsm_x4(uint32_t* r, uint32_t addr) {
    asm volatile("ldmatrix.sync.aligned.m8n8.x4.shared.b16 {%0,%1,%2,%3}, [%4];"
                 : "=r"(r[0]), "=r"(r[1]), "=r"(r[2]), "=r"(r[3]) : "r"(addr));
}
__device__ __forceinline__ void ldsm_x4_t(uint32_t* r, uint32_t addr) {
    asm volatile("ldmatrix.sync.aligned.m8n8.x4.trans.shared.b16 {%0,%1,%2,%3}, [%4];"
                 : "=r"(r[0]), "=r"(r[1]), "=r"(r[2]), "=r"(r[3]) : "r"(addr));
}
__device__ __forceinline__ void mma_bf16(float* c, const uint32_t* a,
                                         uint32_t b0, uint32_t b1) {
    asm volatile(
        "mma.sync.aligned.m16n8k16.row.col.f32.bf16.bf16.f32 "
        "{%0,%1,%2,%3}, {%4,%5,%6,%7}, {%8,%9}, {%0,%1,%2,%3};"
        : "+f"(c[0]), "+f"(c[1]), "+f"(c[2]), "+f"(c[3])
        : "r"(a[0]), "r"(a[1]), "r"(a[2]), "r"(a[3]), "r"(b0), "r"(b1));
}

__global__ void __launch_bounds__(256) k_gemm1_mma(const float* __restrict__ x,
                                                   const float* __restrict__ W1) {
    __shared__ __align__(16) __nv_bfloat16 Ah[128][40];
    __shared__ __align__(16) __nv_bfloat16 Al[128][40];
    __shared__ __align__(16) __nv_bfloat16 Wh[32][136];
    __shared__ __align__(16) __nv_bfloat16 Wl[32][136];

    int tid = threadIdx.x;
    int wid = tid >> 5, lane = tid & 31;
    int warp_m = wid >> 1, warp_n = wid & 1;
    int brow = blockIdx.x * 128;

    float c[2][8][4];
#pragma unroll
    for (int i = 0; i < 2; i++)
#pragma unroll
        for (int j = 0; j < 8; j++)
#pragma unroll
            for (int k = 0; k < 4; k++) c[i][j][k] = 0.f;

    for (int k0 = 0; k0 < 128; k0 += 32) {
        // stage A chunk: 128 rows x 32 k (hi/lo)
#pragma unroll
        for (int it = 0; it < 4; it++) {
            int idx = tid + it * 256;
            int r = idx >> 3, kq = idx & 7;
            int row = brow + r;
            float4 v = make_float4(0.f, 0.f, 0.f, 0.f);
            if (row < N_NODES)
                v = *(const float4*)(x + (size_t)row * 128 + k0 + kq * 4);
            __nv_bfloat16 hx = __float2bfloat16(v.x);
            __nv_bfloat16 hy = __float2bfloat16(v.y);
            __nv_bfloat16 hz = __float2bfloat16(v.z);
            __nv_bfloat16 hw = __float2bfloat16(v.w);
            Ah[r][kq * 4 + 0] = hx;
            Ah[r][kq * 4 + 1] = hy;
            Ah[r][kq * 4 + 2] = hz;
            Ah[r][kq * 4 + 3] = hw;
            Al[r][kq * 4 + 0] = __float2bfloat16(v.x - __bfloat162float(hx));
            Al[r][kq * 4 + 1] = __float2bfloat16(v.y - __bfloat162float(hy));
            Al[r][kq * 4 + 2] = __float2bfloat16(v.z - __bfloat162float(hz));
            Al[r][kq * 4 + 3] = __float2bfloat16(v.w - __bfloat162float(hw));
        }
        // stage W chunk: 32 k x 128 n (hi/lo)
#pragma unroll
        for (int it = 0; it < 4; it++) {
            int idx = tid + it * 256;
            int r = idx >> 5, cq = idx & 31;
            float4 v = *(const float4*)(W1 + (size_t)(k0 + r) * 128 + cq * 4);
            __nv_bfloat16 hx = __float2bfloat16(v.x);
            __nv_bfloat16 hy = __float2bfloat16(v.y);
            __nv_bfloat16 hz = __float2bfloat16(v.z);
            __nv_bfloat16 hw = __float2bfloat16(v.w);
            Wh[r][cq * 4 + 0] = hx;
            Wh[r][cq * 4 + 1] = hy;
            Wh[r][cq * 4 + 2] = hz;
            Wh[r][cq * 4 + 3] = hw;
            Wl[r][cq * 4 + 0] = __float2bfloat16(v.x - __bfloat162float(hx));
            Wl[r][cq * 4 + 1] = __float2bfloat16(v.y - __bfloat162float(hy));
            Wl[r][cq * 4 + 2] = __float2bfloat16(v.z - __bfloat162float(hz));
            Wl[r][cq * 4 + 3] = __float2bfloat16(v.w - __bfloat162float(hw));
        }
        __syncthreads();

        uint32_t ah = smem_u32(&Ah[0][0]);
        uint32_t al = smem_u32(&Al[0][0]);
        uint32_t wh = smem_u32(&Wh[0][0]);
        uint32_t wl = smem_u32(&Wl[0][0]);
        uint32_t abase_p[3] = {ah, al, ah};
        uint32_t bbase_p[3] = {wh, wh, wl};

#pragma unroll
        for (int pass = 0; pass < 3; pass++) {
            uint32_t abase = abase_p[pass];
            uint32_t bbase = bbase_p[pass];
#pragma unroll
            for (int ko = 0; ko < 32; ko += 16) {
                uint32_t a[2][4];
#pragma unroll
                for (int mt = 0; mt < 2; mt++) {
                    int row = warp_m * 32 + mt * 16 + (lane & 15);
                    int kp = ko + ((lane >> 4) << 3);
                    ldsm_x4(a[mt], abase + (uint32_t)(row * 40 + kp) * 2u);
                }
#pragma unroll
                for (int nt = 0; nt < 4; nt++) {
                    int n0 = warp_n * 64 + nt * 16;
                    int krow = ko + ((lane >> 3) & 1) * 8 + (lane & 7);
                    int ncol = n0 + (lane >> 4) * 8;
                    uint32_t b[4];
                    ldsm_x4_t(b, bbase + (uint32_t)(krow * 136 + ncol) * 2u);
                    mma_bf16(c[0][nt * 2 + 0], a[0], b[0], b[1]);
                    mma_bf16(c[0][nt * 2 + 1], a[0], b[2], b[3]);
                    mma_bf16(c[1][nt * 2 + 0], a[1], b[0], b[1]);
                    mma_bf16(c[1][nt * 2 + 1], a[1], b[2], b[3]);
                }
            }
        }
        __syncthreads();
    }

    // epilogue: c[mt][nf]: rows warp_m*32+mt*16+{g, g+8}, cols warp_n*64+nf*8+2*tig
    int g = lane >> 2, tig = lane & 3;
#pragma unroll
    for (int mt = 0; mt < 2; mt++) {
        int r0 = brow + warp_m * 32 + mt * 16 + g;
#pragma unroll
        for (int nf = 0; nf < 8; nf++) {
            int n = warp_n * 64 + nf * 8 + tig * 2;
            if (r0 < N_NODES)
                *(float2*)(g_xs1 + (size_t)r0 * 128 + n) =
                    make_float2(c[mt][nf][0], c[mt][nf][1]);
            if (r0 + 8 < N_NODES)
                *(float2*)(g_xs1 + (size_t)(r0 + 8) * 128 + n) =
                    make_float2(c[mt][nf][2], c[mt][nf][3]);
        }
    }
}

// ---------------- scalar GEMM (R10 shape): out = (in @ W) * dinv --------------
template <int NOUT, bool SCALE>
__device__ __forceinline__ void gemm_body(const float* __restrict__ in,
                                          const float* __restrict__ W,
                                          float* __restrict__ out) {
    constexpr int BM = 128, BK = 32, TM = 8, TN = NOUT / 16, TP = TN / 2;
    __shared__ __align__(16) float xt[BK][BM + 4];
    __shared__ __align__(16) float ws[BK][NOUT];

    int tid = threadIdx.x;
    int tcol = tid & 15;
    int trow = tid >> 4;
    int brow = blockIdx.x * BM;

    unsigned long long acc[TM][TP];
#pragma unroll
    for (int i = 0; i < TM; i++)
#pragma unroll
        for (int j = 0; j < TP; j++) acc[i][j] = 0ull;

    for (int k0 = 0; k0 < 128; k0 += BK) {
#pragma unroll
        for (int it = 0; it < BM * BK / (4 * 256); it++) {
            int idx = tid + it * 256;
            int r = idx >> 3;
            int kq = idx & 7;
            int row = brow + r;
            float4 v = make_float4(0.f, 0.f, 0.f, 0.f);
            if (row < N_NODES)
                v = *(const float4*)(in + row * 128 + k0 + kq * 4);
            xt[kq * 4 + 0][r] = v.x;
            xt[kq * 4 + 1][r] = v.y;
            xt[kq * 4 + 2][r] = v.z;
            xt[kq * 4 + 3][r] = v.w;
        }
#pragma unroll
        for (int it = 0; it < BK * NOUT / (4 * 256); it++) {
            int idx = tid + it * 256;
            int r = idx / (NOUT / 4);
            int cq = idx % (NOUT / 4);
            *(float4*)(&ws[r][cq * 4]) = *(const float4*)(W + (k0 + r) * NOUT + cq * 4);
        }
        __syncthreads();

#pragma unroll 4
        for (int kk = 0; kk < BK; kk++) {
            float4 a0 = *(const float4*)(&xt[kk][trow * TM]);
            float4 a1 = *(const float4*)(&xt[kk][trow * TM + 4]);
            unsigned long long pa[TM];
            pa[0] = pack2(a0.x); pa[1] = pack2(a0.y);
            pa[2] = pack2(a0.z); pa[3] = pack2(a0.w);
            pa[4] = pack2(a1.x); pa[5] = pack2(a1.y);
            pa[6] = pack2(a1.z); pa[7] = pack2(a1.w);

            unsigned long long b[TP];
#pragma unroll
            for (int j = 0; j < TP; j += 2) {
                ulonglong2 bv = *(const ulonglong2*)(&ws[kk][tcol * TN + j * 2]);
                b[j] = bv.x;
                b[j + 1] = bv.y;
            }
#pragma unroll
            for (int i = 0; i < TM; i++)
#pragma unroll
                for (int j = 0; j < TP; j++) acc[i][j] = ffma2(pa[i], b[j], acc[i][j]);
        }
        __syncthreads();
    }

#pragma unroll
    for (int i = 0; i < TM; i++) {
        int row = brow + trow * TM + i;
        if (row < N_NODES) {
            float di = SCALE ? g_dinv[row] : 1.0f;
            float r[TN];
#pragma unroll
            for (int j = 0; j < TP; j++) {
                float2 u = unpack2(acc[i][j]);
                r[j * 2] = u.x * di;
                r[j * 2 + 1] = u.y * di;
            }
#pragma unroll
            for (int j = 0; j < TN; j += 4)
                *(float4*)(out + row * NOUT + tcol * TN + j) =
                    make_float4(r[j], r[j + 1], r[j + 2], r[j + 3]);
        }
    }
}

__global__ void __launch_bounds__(256) k_gemm2(const float* __restrict__ W2) {
    gemm_body<OUT_CH, true>(g_h, W2, g_xs2);
}

// ---------------- aggregation layer 1: warp per node, 128 feats ----------------
__global__ void __launch_bounds__(256) k_agg1(const float* __restrict__ b1) {
    int gw = (blockIdx.x * blockDim.x + threadIdx.x) >> 5;
    int lane = threadIdx.x & 31;
    if (gw >= N_NODES) return;
    int v = gw;

    const float4* xrow = (const float4*)g_xs1;
    float dvv = g_dinv[v];
    float4 self = xrow[v * 32 + lane];
    float4 acc;
    acc.x = self.x * dvv; acc.y = self.y * dvv;
    acc.z = self.z * dvv; acc.w = self.w * dvv;

    int deg = g_cnt[v];
    int base = v * MAXDEG;
    for (int e = 0; e < deg; e += 32) {
        int m = deg - e;
        int c = 0;
        float dv = 0.f;
        if (lane < m) {
            c = g_ell[base + e + lane];
            dv = g_dinv[c];
        }
        if (m >= 32) {
#pragma unroll
            for (int j = 0; j < 32; j++) {
                int col = __shfl_sync(0xffffffffu, c, j);
                float d = __shfl_sync(0xffffffffu, dv, j);
                float4 val = xrow[col * 32 + lane];
                acc.x = fmaf(val.x, d, acc.x);
                acc.y = fmaf(val.y, d, acc.y);
                acc.z = fmaf(val.z, d, acc.z);
                acc.w = fmaf(val.w, d, acc.w);
            }
        } else {
            for (int j = 0; j < m; j++) {
                int col = __shfl_sync(0xffffffffu, c, j);
                float d = __shfl_sync(0xffffffffu, dv, j);
                float4 val = xrow[col * 32 + lane];
                acc.x = fmaf(val.x, d, acc.x);
                acc.y = fmaf(val.y, d, acc.y);
                acc.z = fmaf(val.z, d, acc.z);
                acc.w = fmaf(val.w, d, acc.w);
            }
        }
    }

    float4 bb = ((const float4*)b1)[lane];
    float4 h;
    h.x = fmaxf(fmaf(dvv, acc.x, bb.x), 0.f);
    h.y = fmaxf(fmaf(dvv, acc.y, bb.y), 0.f);
    h.z = fmaxf(fmaf(dvv, acc.z, bb.z), 0.f);
    h.w = fmaxf(fmaf(dvv, acc.w, bb.w), 0.f);

    float ss = h.x * h.x + h.y * h.y + h.z * h.z + h.w * h.w;
#pragma unroll
    for (int off = 16; off; off >>= 1) ss += __shfl_xor_sync(0xffffffffu, ss, off);
    float sc = 1.0f / fmaxf(sqrtf(ss), 1e-12f);
    h.x *= sc; h.y *= sc; h.z *= sc; h.w *= sc;

    ((float4*)g_h)[v * 32 + lane] = h;
}

// ---------------- aggregation layer 2: warp per node, 64 feats ----------------
__global__ void __launch_bounds__(256) k_agg2(const float* __restrict__ b2,
                                              float* __restrict__ out) {
    int gw = (blockIdx.x * blockDim.x + threadIdx.x) >> 5;
    int lane = threadIdx.x & 31;
    if (gw >= N_NODES) return;
    int v = gw;

    const float2* xrow = (const float2*)g_xs2;
    float2 acc = xrow[v * 32 + lane];  // self term

    int deg = g_cnt[v];
    int base = v * MAXDEG;
    for (int e = 0; e < deg; e += 32) {
        int m = deg - e;
        int c = (lane < m) ? g_ell[base + e + lane] : 0;
        if (m >= 32) {
#pragma unroll
            for (int j = 0; j < 32; j++) {
                int col = __shfl_sync(0xffffffffu, c, j);
                float2 val = xrow[col * 32 + lane];
                acc.x += val.x; acc.y += val.y;
            }
        } else {
            for (int j = 0; j < m; j++) {
                int col = __shfl_sync(0xffffffffu, c, j);
                float2 val = xrow[col * 32 + lane];
                acc.x += val.x; acc.y += val.y;
            }
        }
    }

    float di = g_dinv[v];
    float2 bb = ((const float2*)b2)[lane];
    float2 o;
    o.x = fmaf(di, acc.x, bb.x);
    o.y = fmaf(di, acc.y, bb.y);
    ((float2*)out)[v * 32 + lane] = o;
}

// ---------------- launch (prep chain forked onto a side stream) ----------------
static cudaStream_t s_side = nullptr;
static cudaEvent_t e_fork = nullptr, e_join = nullptr;

extern "C" void kernel_launch(void* const* d_in, const int* in_sizes, int n_in,
                              void* d_out, int out_size) {
    const float* x  = (const float*)d_in[0];
    const int*   ei = (const int*)d_in[1];   // JAX default: int64 request -> int32
    const float* W1 = (const float*)d_in[2];
    const float* b1 = (const float*)d_in[3];
    const float* W2 = (const float*)d_in[4];
    const float* b2 = (const float*)d_in[5];
    float* out = (float*)d_out;

    if (!s_side) {  // first call is the uncaptured correctness run
        cudaStreamCreateWithFlags(&s_side, cudaStreamNonBlocking);
        cudaEventCreateWithFlags(&e_fork, cudaEventDisableTiming);
        cudaEventCreateWithFlags(&e_join, cudaEventDisableTiming);
    }

    // fork: ELL prep on side stream, tensor gemm1 on main stream
    cudaEventRecord(e_fork, 0);
    cudaStreamWaitEvent(s_side, e_fork, 0);

    k_zero_cnt<<<(N_NODES + 255) / 256, 256, 0, s_side>>>();
    k_scatter_ell<<<(N_EDGES + 255) / 256, 256, 0, s_side>>>(ei);
    k_dinv<<<(N_NODES + 255) / 256, 256, 0, s_side>>>();
    cudaEventRecord(e_join, s_side);

    k_gemm1_mma<<<(N_NODES + 127) / 128, 256>>>(x, W1);

    // join: everything below needs both gemm1 and the ELL/dinv
    cudaStreamWaitEvent(0, e_join, 0);

    k_agg1<<<(N_NODES * 32 + 255) / 256, 256>>>(b1);
    k_gemm2<<<(N_NODES + 127) / 128, 256>>>(W2);
    k_agg2<<<(N_NODES * 32 + 255) / 256, 256>>>(b2, out);
}

// round 16
// speedup vs baseline: 1.4126x; 1.0205x over previous
#include <cuda_runtime.h>
#include <cuda_bf16.h>
#include <cstdint>

#define N_NODES 100000
#define N_EDGES 1600000
#define IN_CH 128
#define HID 128
#define OUT_CH 64
#define MAXDEG 64

// ---------------- scratch (static device globals; no allocation) ----------------
__device__ int   g_cnt[N_NODES];
__device__ int   g_ell[N_NODES * MAXDEG];          // ELL adjacency (by dst)
__device__ float g_dinv[N_NODES];
__device__ __nv_bfloat16 g_xs1h[N_NODES * HID];    // x @ W1 (bf16)
__device__ float g_h  [N_NODES * HID];             // layer-1 activations (fp32)
__device__ __nv_bfloat16 g_xs2h[N_NODES * OUT_CH]; // (h @ W2) * dinv (bf16)

// ---------------- f32x2 packed-FMA helpers (scalar gemm2) ----------------
__device__ __forceinline__ unsigned long long ffma2(unsigned long long a,
                                                    unsigned long long b,
                                                    unsigned long long c) {
    unsigned long long d;
    asm("fma.rn.f32x2 %0, %1, %2, %3;" : "=l"(d) : "l"(a), "l"(b), "l"(c));
    return d;
}
__device__ __forceinline__ unsigned long long pack2(float x) {
    unsigned long long d;
    asm("mov.b64 %0, {%1, %1};" : "=l"(d) : "f"(x));
    return d;
}
__device__ __forceinline__ float2 unpack2(unsigned long long v) {
    float2 r;
    asm("mov.b64 {%0, %1}, %2;" : "=f"(r.x), "=f"(r.y) : "l"(v));
    return r;
}

__device__ __forceinline__ uint32_t smem_u32(const void* p) {
    uint32_t a;
    asm("{ .reg .u64 t; cvta.to.shared.u64 t, %1; cvt.u32.u64 %0, t; }"
        : "=r"(a) : "l"(p));
    return a;
}

// ---------------- prep: ELL build ----------------
__global__ void k_zero_cnt() {
    int i = blockIdx.x * blockDim.x + threadIdx.x;
    if (i < N_NODES) g_cnt[i] = 0;
}
__global__ void k_scatter_ell(const int* __restrict__ ei) {
    int e = blockIdx.x * blockDim.x + threadIdx.x;
    if (e < N_EDGES) {
        int src = ei[e];
        int dst = ei[N_EDGES + e];
        int slot = atomicAdd(&g_cnt[dst], 1);
        g_ell[dst * MAXDEG + slot] = src;
    }
}
__global__ void k_dinv() {
    int i = blockIdx.x * blockDim.x + threadIdx.x;
    if (i < N_NODES) g_dinv[i] = rsqrtf((float)(g_cnt[i] + 1));  // +1 self loop
}

// ---------------- tensor GEMM1 via mma.sync (bf16 hi/lo, 3 passes) ------------
__device__ __forceinline__ void ldsm_x4(uint32_t* r, uint32_t addr) {
    asm volatile("ldmatrix.sync.aligned.m8n8.x4.shared.b16 {%0,%1,%2,%3}, [%4];"
                 : "=r"(r[0]), "=r"(r[1]), "=r"(r[2]), "=r"(r[3]) : "r"(addr));
}
__device__ __forceinline__ void ldsm_x4_t(uint32_t* r, uint32_t addr) {
    asm volatile("ldmatrix.sync.aligned.m8n8.x4.trans.shared.b16 {%0,%1,%2,%3}, [%4];"
                 : "=r"(r[0]), "=r"(r[1]), "=r"(r[2]), "=r"(r[3]) : "r"(addr));
}
__device__ __forceinline__ void mma_bf16(float* c, const uint32_t* a,
                                         uint32_t b0, uint32_t b1) {
    asm volatile(
        "mma.sync.aligned.m16n8k16.row.col.f32.bf16.bf16.f32 "
        "{%0,%1,%2,%3}, {%4,%5,%6,%7}, {%8,%9}, {%0,%1,%2,%3};"
        : "+f"(c[0]), "+f"(c[1]), "+f"(c[2]), "+f"(c[3])
        : "r"(a[0]), "r"(a[1]), "r"(a[2]), "r"(a[3]), "r"(b0), "r"(b1));
}

__global__ void __launch_bounds__(256) k_gemm1_mma(const float* __restrict__ x,
                                                   const float* __restrict__ W1) {
    __shared__ __align__(16) __nv_bfloat16 Ah[128][40];
    __shared__ __align__(16) __nv_bfloat16 Al[128][40];
    __shared__ __align__(16) __nv_bfloat16 Wh[32][136];
    __shared__ __align__(16) __nv_bfloat16 Wl[32][136];

    int tid = threadIdx.x;
    int wid = tid >> 5, lane = tid & 31;
    int warp_m = wid >> 1, warp_n = wid & 1;
    int brow = blockIdx.x * 128;

    float c[2][8][4];
#pragma unroll
    for (int i = 0; i < 2; i++)
#pragma unroll
        for (int j = 0; j < 8; j++)
#pragma unroll
            for (int k = 0; k < 4; k++) c[i][j][k] = 0.f;

    for (int k0 = 0; k0 < 128; k0 += 32) {
#pragma unroll
        for (int it = 0; it < 4; it++) {
            int idx = tid + it * 256;
            int r = idx >> 3, kq = idx & 7;
            int row = brow + r;
            float4 v = make_float4(0.f, 0.f, 0.f, 0.f);
            if (row < N_NODES)
                v = *(const float4*)(x + (size_t)row * 128 + k0 + kq * 4);
            __nv_bfloat16 hx = __float2bfloat16(v.x);
            __nv_bfloat16 hy = __float2bfloat16(v.y);
            __nv_bfloat16 hz = __float2bfloat16(v.z);
            __nv_bfloat16 hw = __float2bfloat16(v.w);
            Ah[r][kq * 4 + 0] = hx;
            Ah[r][kq * 4 + 1] = hy;
            Ah[r][kq * 4 + 2] = hz;
            Ah[r][kq * 4 + 3] = hw;
            Al[r][kq * 4 + 0] = __float2bfloat16(v.x - __bfloat162float(hx));
            Al[r][kq * 4 + 1] = __float2bfloat16(v.y - __bfloat162float(hy));
            Al[r][kq * 4 + 2] = __float2bfloat16(v.z - __bfloat162float(hz));
            Al[r][kq * 4 + 3] = __float2bfloat16(v.w - __bfloat162float(hw));
        }
#pragma unroll
        for (int it = 0; it < 4; it++) {
            int idx = tid + it * 256;
            int r = idx >> 5, cq = idx & 31;
            float4 v = *(const float4*)(W1 + (size_t)(k0 + r) * 128 + cq * 4);
            __nv_bfloat16 hx = __float2bfloat16(v.x);
            __nv_bfloat16 hy = __float2bfloat16(v.y);
            __nv_bfloat16 hz = __float2bfloat16(v.z);
            __nv_bfloat16 hw = __float2bfloat16(v.w);
            Wh[r][cq * 4 + 0] = hx;
            Wh[r][cq * 4 + 1] = hy;
            Wh[r][cq * 4 + 2] = hz;
            Wh[r][cq * 4 + 3] = hw;
            Wl[r][cq * 4 + 0] = __float2bfloat16(v.x - __bfloat162float(hx));
            Wl[r][cq * 4 + 1] = __float2bfloat16(v.y - __bfloat162float(hy));
            Wl[r][cq * 4 + 2] = __float2bfloat16(v.z - __bfloat162float(hz));
            Wl[r][cq * 4 + 3] = __float2bfloat16(v.w - __bfloat162float(hw));
        }
        __syncthreads();

        uint32_t ah = smem_u32(&Ah[0][0]);
        uint32_t al = smem_u32(&Al[0][0]);
        uint32_t wh = smem_u32(&Wh[0][0]);
        uint32_t wl = smem_u32(&Wl[0][0]);
        uint32_t abase_p[3] = {ah, al, ah};
        uint32_t bbase_p[3] = {wh, wh, wl};

#pragma unroll
        for (int pass = 0; pass < 3; pass++) {
            uint32_t abase = abase_p[pass];
            uint32_t bbase = bbase_p[pass];
#pragma unroll
            for (int ko = 0; ko < 32; ko += 16) {
                uint32_t a[2][4];
#pragma unroll
                for (int mt = 0; mt < 2; mt++) {
                    int row = warp_m * 32 + mt * 16 + (lane & 15);
                    int kp = ko + ((lane >> 4) << 3);
                    ldsm_x4(a[mt], abase + (uint32_t)(row * 40 + kp) * 2u);
                }
#pragma unroll
                for (int nt = 0; nt < 4; nt++) {
                    int n0 = warp_n * 64 + nt * 16;
                    int krow = ko + ((lane >> 3) & 1) * 8 + (lane & 7);
                    int ncol = n0 + (lane >> 4) * 8;
                    uint32_t b[4];
                    ldsm_x4_t(b, bbase + (uint32_t)(krow * 136 + ncol) * 2u);
                    mma_bf16(c[0][nt * 2 + 0], a[0], b[0], b[1]);
                    mma_bf16(c[0][nt * 2 + 1], a[0], b[2], b[3]);
                    mma_bf16(c[1][nt * 2 + 0], a[1], b[0], b[1]);
                    mma_bf16(c[1][nt * 2 + 1], a[1], b[2], b[3]);
                }
            }
        }
        __syncthreads();
    }

    // epilogue -> bf16 xs1
    int g = lane >> 2, tig = lane & 3;
#pragma unroll
    for (int mt = 0; mt < 2; mt++) {
        int r0 = brow + warp_m * 32 + mt * 16 + g;
#pragma unroll
        for (int nf = 0; nf < 8; nf++) {
            int n = warp_n * 64 + nf * 8 + tig * 2;
            if (r0 < N_NODES)
                *(__nv_bfloat162*)(g_xs1h + (size_t)r0 * 128 + n) =
                    __floats2bfloat162_rn(c[mt][nf][0], c[mt][nf][1]);
            if (r0 + 8 < N_NODES)
                *(__nv_bfloat162*)(g_xs1h + (size_t)(r0 + 8) * 128 + n) =
                    __floats2bfloat162_rn(c[mt][nf][2], c[mt][nf][3]);
        }
    }
}

// ---------------- scalar GEMM2: xs2h = (g_h @ W2) * dinv, bf16 out ------------
__global__ void __launch_bounds__(256) k_gemm2(const float* __restrict__ W2) {
    constexpr int NOUT = OUT_CH;
    constexpr int BM = 128, BK = 32, TM = 8, TN = NOUT / 16, TP = TN / 2;
    __shared__ __align__(16) float xt[BK][BM + 4];
    __shared__ __align__(16) float ws[BK][NOUT];

    int tid = threadIdx.x;
    int tcol = tid & 15;
    int trow = tid >> 4;
    int brow = blockIdx.x * BM;

    unsigned long long acc[TM][TP];
#pragma unroll
    for (int i = 0; i < TM; i++)
#pragma unroll
        for (int j = 0; j < TP; j++) acc[i][j] = 0ull;

    for (int k0 = 0; k0 < 128; k0 += BK) {
#pragma unroll
        for (int it = 0; it < BM * BK / (4 * 256); it++) {
            int idx = tid + it * 256;
            int r = idx >> 3;
            int kq = idx & 7;
            int row = brow + r;
            float4 v = make_float4(0.f, 0.f, 0.f, 0.f);
            if (row < N_NODES)
                v = *(const float4*)(g_h + (size_t)row * 128 + k0 + kq * 4);
            xt[kq * 4 + 0][r] = v.x;
            xt[kq * 4 + 1][r] = v.y;
            xt[kq * 4 + 2][r] = v.z;
            xt[kq * 4 + 3][r] = v.w;
        }
#pragma unroll
        for (int it = 0; it < BK * NOUT / (4 * 256); it++) {
            int idx = tid + it * 256;
            int r = idx / (NOUT / 4);
            int cq = idx % (NOUT / 4);
            *(float4*)(&ws[r][cq * 4]) = *(const float4*)(W2 + (k0 + r) * NOUT + cq * 4);
        }
        __syncthreads();

#pragma unroll 4
        for (int kk = 0; kk < BK; kk++) {
            float4 a0 = *(const float4*)(&xt[kk][trow * TM]);
            float4 a1 = *(const float4*)(&xt[kk][trow * TM + 4]);
            unsigned long long pa[TM];
            pa[0] = pack2(a0.x); pa[1] = pack2(a0.y);
            pa[2] = pack2(a0.z); pa[3] = pack2(a0.w);
            pa[4] = pack2(a1.x); pa[5] = pack2(a1.y);
            pa[6] = pack2(a1.z); pa[7] = pack2(a1.w);

            unsigned long long b[TP];
            {
                ulonglong2 bv = *(const ulonglong2*)(&ws[kk][tcol * TN]);
                b[0] = bv.x;
                b[1] = bv.y;
            }
#pragma unroll
            for (int i = 0; i < TM; i++)
#pragma unroll
                for (int j = 0; j < TP; j++) acc[i][j] = ffma2(pa[i], b[j], acc[i][j]);
        }
        __syncthreads();
    }

#pragma unroll
    for (int i = 0; i < TM; i++) {
        int row = brow + trow * TM + i;
        if (row < N_NODES) {
            float di = g_dinv[row];
            float2 u0 = unpack2(acc[i][0]);
            float2 u1 = unpack2(acc[i][1]);
            __nv_bfloat162 p0 = __floats2bfloat162_rn(u0.x * di, u0.y * di);
            __nv_bfloat162 p1 = __floats2bfloat162_rn(u1.x * di, u1.y * di);
            uint2 st;
            st.x = *reinterpret_cast<uint32_t*>(&p0);
            st.y = *reinterpret_cast<uint32_t*>(&p1);
            *(uint2*)(g_xs2h + (size_t)row * NOUT + tcol * TN) = st;
        }
    }
}

// ---------------- aggregation layer 1: warp per node, 128 bf16 feats ----------
// h[v] = l2norm(relu(dinv[v]*(sum dinv[src]*xs1[src] + dinv[v]*xs1[v]) + b1))
__global__ void __launch_bounds__(256) k_agg1(const float* __restrict__ b1) {
    int gw = (blockIdx.x * blockDim.x + threadIdx.x) >> 5;
    int lane = threadIdx.x & 31;
    if (gw >= N_NODES) return;
    int v = gw;

    const uint2* xrow = (const uint2*)g_xs1h;   // 128 bf16 = 32 uint2 per row
    float dvv = g_dinv[v];

    uint2 s = xrow[(size_t)v * 32 + lane];
    float2 s0 = __bfloat1622float2(*reinterpret_cast<__nv_bfloat162*>(&s.x));
    float2 s1 = __bfloat1622float2(*reinterpret_cast<__nv_bfloat162*>(&s.y));
    float4 acc;
    acc.x = s0.x * dvv; acc.y = s0.y * dvv;
    acc.z = s1.x * dvv; acc.w = s1.y * dvv;

    int deg = g_cnt[v];
    int base = v * MAXDEG;
    for (int e = 0; e < deg; e += 32) {
        int m = deg - e;
        int c = 0;
        float dv = 0.f;
        if (lane < m) {
            c = g_ell[base + e + lane];
            dv = g_dinv[c];
        }
        if (m >= 32) {
#pragma unroll
            for (int j = 0; j < 32; j++) {
                int col = __shfl_sync(0xffffffffu, c, j);
                float d = __shfl_sync(0xffffffffu, dv, j);
                uint2 u = xrow[(size_t)col * 32 + lane];
                float2 f0 = __bfloat1622float2(*reinterpret_cast<__nv_bfloat162*>(&u.x));
                float2 f1 = __bfloat1622float2(*reinterpret_cast<__nv_bfloat162*>(&u.y));
                acc.x = fmaf(f0.x, d, acc.x);
                acc.y = fmaf(f0.y, d, acc.y);
                acc.z = fmaf(f1.x, d, acc.z);
                acc.w = fmaf(f1.y, d, acc.w);
            }
        } else {
            for (int j = 0; j < m; j++) {
                int col = __shfl_sync(0xffffffffu, c, j);
                float d = __shfl_sync(0xffffffffu, dv, j);
                uint2 u = xrow[(size_t)col * 32 + lane];
                float2 f0 = __bfloat1622float2(*reinterpret_cast<__nv_bfloat162*>(&u.x));
                float2 f1 = __bfloat1622float2(*reinterpret_cast<__nv_bfloat162*>(&u.y));
                acc.x = fmaf(f0.x, d, acc.x);
                acc.y = fmaf(f0.y, d, acc.y);
                acc.z = fmaf(f1.x, d, acc.z);
                acc.w = fmaf(f1.y, d, acc.w);
            }
        }
    }

    float4 bb = ((const float4*)b1)[lane];
    float4 h;
    h.x = fmaxf(fmaf(dvv, acc.x, bb.x), 0.f);
    h.y = fmaxf(fmaf(dvv, acc.y, bb.y), 0.f);
    h.z = fmaxf(fmaf(dvv, acc.z, bb.z), 0.f);
    h.w = fmaxf(fmaf(dvv, acc.w, bb.w), 0.f);

    float ss = h.x * h.x + h.y * h.y + h.z * h.z + h.w * h.w;
#pragma unroll
    for (int off = 16; off; off >>= 1) ss += __shfl_xor_sync(0xffffffffu, ss, off);
    float sc = 1.0f / fmaxf(sqrtf(ss), 1e-12f);
    h.x *= sc; h.y *= sc; h.z *= sc; h.w *= sc;

    ((float4*)g_h)[(size_t)v * 32 + lane] = h;
}

// ---------------- aggregation layer 2: warp per node, 64 bf16 feats -----------
// out[v] = dinv[v]*(sum xs2[src] + xs2[v]) + b2
__global__ void __launch_bounds__(256) k_agg2(const float* __restrict__ b2,
                                              float* __restrict__ out) {
    int gw = (blockIdx.x * blockDim.x + threadIdx.x) >> 5;
    int lane = threadIdx.x & 31;
    if (gw >= N_NODES) return;
    int v = gw;

    const uint32_t* xrow = (const uint32_t*)g_xs2h;  // 64 bf16 = 32 u32 per row
    uint32_t su = xrow[(size_t)v * 32 + lane];
    float2 acc = __bfloat1622float2(*reinterpret_cast<__nv_bfloat162*>(&su));

    int deg = g_cnt[v];
    int base = v * MAXDEG;
    for (int e = 0; e < deg; e += 32) {
        int m = deg - e;
        int c = (lane < m) ? g_ell[base + e + lane] : 0;
        if (m >= 32) {
#pragma unroll
            for (int j = 0; j < 32; j++) {
                int col = __shfl_sync(0xffffffffu, c, j);
                uint32_t u = xrow[(size_t)col * 32 + lane];
                float2 f = __bfloat1622float2(*reinterpret_cast<__nv_bfloat162*>(&u));
                acc.x += f.x; acc.y += f.y;
            }
        } else {
            for (int j = 0; j < m; j++) {
                int col = __shfl_sync(0xffffffffu, c, j);
                uint32_t u = xrow[(size_t)col * 32 + lane];
                float2 f = __bfloat1622float2(*reinterpret_cast<__nv_bfloat162*>(&u));
                acc.x += f.x; acc.y += f.y;
            }
        }
    }

    float di = g_dinv[v];
    float2 bb = ((const float2*)b2)[lane];
    float2 o;
    o.x = fmaf(di, acc.x, bb.x);
    o.y = fmaf(di, acc.y, bb.y);
    ((float2*)out)[(size_t)v * 32 + lane] = o;
}

// ---------------- launch (prep chain forked onto a side stream) ----------------
static cudaStream_t s_side = nullptr;
static cudaEvent_t e_fork = nullptr, e_join = nullptr;

extern "C" void kernel_launch(void* const* d_in, const int* in_sizes, int n_in,
                              void* d_out, int out_size) {
    const float* x  = (const float*)d_in[0];
    const int*   ei = (const int*)d_in[1];   // JAX default: int64 request -> int32
    const float* W1 = (const float*)d_in[2];
    const float* b1 = (const float*)d_in[3];
    const float* W2 = (const float*)d_in[4];
    const float* b2 = (const float*)d_in[5];
    float* out = (float*)d_out;

    if (!s_side) {  // first call is the uncaptured correctness run
        cudaStreamCreateWithFlags(&s_side, cudaStreamNonBlocking);
        cudaEventCreateWithFlags(&e_fork, cudaEventDisableTiming);
        cudaEventCreateWithFlags(&e_join, cudaEventDisableTiming);
    }

    // fork: ELL prep on side stream, tensor gemm1 on main stream
    cudaEventRecord(e_fork, 0);
    cudaStreamWaitEvent(s_side, e_fork, 0);

    k_zero_cnt<<<(N_NODES + 255) / 256, 256, 0, s_side>>>();
    k_scatter_ell<<<(N_EDGES + 255) / 256, 256, 0, s_side>>>(ei);
    k_dinv<<<(N_NODES + 255) / 256, 256, 0, s_side>>>();
    cudaEventRecord(e_join, s_side);

    k_gemm1_mma<<<(N_NODES + 127) / 128, 256>>>(x, W1);

    // join: everything below needs both gemm1 and the ELL/dinv
    cudaStreamWaitEvent(0, e_join, 0);

    k_agg1<<<(N_NODES * 32 + 255) / 256, 256>>>(b1);
    k_gemm2<<<(N_NODES + 127) / 128, 256>>>(W2);
    k_agg2<<<(N_NODES * 32 + 255) / 256, 256>>>(b2, out);
}